// round 13
// baseline (speedup 1.0000x reference)
#include <cuda_runtime.h>

// ---------------------------------------------------------------------------
// H3 block: Q/K/V proj -> shift-SSM FIR on K -> per-head KV outer product ->
// S4D diagonal SSM (linear recurrence scan, packed f32x2) -> Q contraction ->
// output projection.  B=1, S=1024, D=512, HEADS=8, DH=64, N=64, DT=0.1
// ---------------------------------------------------------------------------

#define SQ   1024
#define DD   512

__device__ float g_Q [SQ*DD];
__device__ float g_K0[SQ*DD];
__device__ float g_K [SQ*DD];
__device__ float g_V [SQ*DD];
__device__ float g_Ot[DD*SQ];   // pre-WO output, transposed [d][s]

typedef unsigned long long u64t;

__device__ __forceinline__ u64t pack2(float lo, float hi) {
    u64t r; asm("mov.b64 %0, {%1,%2};" : "=l"(r) : "f"(lo), "f"(hi)); return r;
}
__device__ __forceinline__ void unpack2(u64t v, float& lo, float& hi) {
    asm("mov.b64 {%0,%1}, %2;" : "=f"(lo), "=f"(hi) : "l"(v));
}
__device__ __forceinline__ u64t fma2(u64t a, u64t b, u64t c) {
    u64t d; asm("fma.rn.f32x2 %0, %1, %2, %3;" : "=l"(d) : "l"(a), "l"(b), "l"(c)); return d;
}
__device__ __forceinline__ u64t mul2(u64t a, u64t b) {
    u64t d; asm("mul.rn.f32x2 %0, %1, %2;" : "=l"(d) : "l"(a), "l"(b)); return d;
}

// ---------------------------------------------------------------------------
// GEMM 1: C[1024,512] = A @ W^T  (x3 via grid.z), 64x64 tile, double-buffered
// ---------------------------------------------------------------------------
__global__ __launch_bounds__(256) void gemm_qkv(
    const float* __restrict__ A,
    const float* __restrict__ WQ, const float* __restrict__ WK,
    const float* __restrict__ WV)
{
    const float* W = (blockIdx.z == 0) ? WQ : (blockIdx.z == 1) ? WK : WV;
    float*       C = (blockIdx.z == 0) ? g_Q : (blockIdx.z == 1) ? g_K0 : g_V;

    __shared__ __align__(16) float As[2][16][64];
    __shared__ __align__(16) float Bs[2][16][64];

    const int t  = threadIdx.x;
    const int tx = t & 15, ty = t >> 4;
    const int m0 = blockIdx.y * 64, n0 = blockIdx.x * 64;
    const int lr = t >> 2, lk = (t & 3) * 4;

    float4 av = *(const float4*)(A + (m0 + lr) * 512 + lk);
    float4 bv = *(const float4*)(W + (n0 + lr) * 512 + lk);
    As[0][lk+0][lr] = av.x; As[0][lk+1][lr] = av.y; As[0][lk+2][lr] = av.z; As[0][lk+3][lr] = av.w;
    Bs[0][lk+0][lr] = bv.x; Bs[0][lk+1][lr] = bv.y; Bs[0][lk+2][lr] = bv.z; Bs[0][lk+3][lr] = bv.w;
    __syncthreads();

    u64t acc2[4][2] = {};
    int buf = 0;

    for (int k0 = 0; k0 < 512; k0 += 16) {
        if (k0 + 16 < 512) {
            av = *(const float4*)(A + (m0 + lr) * 512 + k0 + 16 + lk);
            bv = *(const float4*)(W + (n0 + lr) * 512 + k0 + 16 + lk);
        }
#pragma unroll
        for (int k = 0; k < 16; k++) {
            float4 a4 = *(const float4*)&As[buf][k][ty * 4];
            float4 b4 = *(const float4*)&Bs[buf][k][tx * 4];
            const u64t b01 = pack2(b4.x, b4.y);
            const u64t b23 = pack2(b4.z, b4.w);
            float ar[4] = {a4.x, a4.y, a4.z, a4.w};
#pragma unroll
            for (int e = 0; e < 4; e++) {
                const u64t ae = pack2(ar[e], ar[e]);
                acc2[e][0] = fma2(ae, b01, acc2[e][0]);
                acc2[e][1] = fma2(ae, b23, acc2[e][1]);
            }
        }
        if (k0 + 16 < 512) {
            const int nb = buf ^ 1;
            As[nb][lk+0][lr] = av.x; As[nb][lk+1][lr] = av.y; As[nb][lk+2][lr] = av.z; As[nb][lk+3][lr] = av.w;
            Bs[nb][lk+0][lr] = bv.x; Bs[nb][lk+1][lr] = bv.y; Bs[nb][lk+2][lr] = bv.z; Bs[nb][lk+3][lr] = bv.w;
            __syncthreads();
            buf = nb;
        }
    }
#pragma unroll
    for (int e = 0; e < 4; e++) {
        float4 v;
        unpack2(acc2[e][0], v.x, v.y);
        unpack2(acc2[e][1], v.z, v.w);
        *(float4*)(C + (m0 + ty * 4 + e) * 512 + n0 + tx * 4) = v;
    }
}

// ---------------------------------------------------------------------------
// Shift-SSM FIR on K (64 taps + skip), one block per channel
// ---------------------------------------------------------------------------
__global__ __launch_bounds__(256) void shift_conv(
    const float* __restrict__ Cs, const float* __restrict__ Ds)
{
    const int d = blockIdx.x;
    __shared__ float taps[64];
    __shared__ float col[1024];
    const int t = threadIdx.x;
    if (t < 64) taps[t] = Cs[d * 64 + t];
    for (int s = t; s < 1024; s += 256) col[s] = g_K0[s * 512 + d];
    __syncthreads();
    const float dsv = Ds[d];
    for (int s = t; s < 1024; s += 256) {
        float acc = dsv * col[s];
        const int tmax = (s < 63) ? s : 63;
        for (int tt = 0; tt <= tmax; tt++) acc += taps[tt] * col[s - tt];
        g_K[s * 512 + d] = acc;
    }
}

// ---------------------------------------------------------------------------
// S4D diagonal SSM scan + Q contraction, batched reduction, float4 staging.
// channel c = h*4096 + i*64 + j,  u[c,s] = K[s,h,i]*V[s,h,j]
//   z' = dA*z + u  (complex),  y = 2Re(sum_n CB*z) + Dd*u
//   O_t[h*64+j][s] = sum_i Q[s,h,i]*y[(h,i,j),s]
//
// grid = 512 (h,j); 256 threads: thread = (i = t>>2, nq = t&3 -> 16 modes).
// 8 packed complex pairs/thread; single packed accumulator (C2re, -C2im).
// K/Q staged TRANSPOSED ([i][r], stride 68, conflict-free LDS.128) so each
// thread fetches 4 steps of K,Q,V with 3 float4 loads. Per-step output
// partial = yp*Q (+skip on nq==0) staged to sVals; every 8 steps one
// block-wide reduce pass (8 LDS + 5 SHFL per thread) emits 8 outputs.
// ---------------------------------------------------------------------------
__global__ __launch_bounds__(256) void scan_s4d(
    const float* __restrict__ Are, const float* __restrict__ Aim,
    const float* __restrict__ Cre, const float* __restrict__ Cim,
    const float* __restrict__ Dd)
{
    const int bx = blockIdx.x;
    const int h = bx >> 6, j = bx & 63;
    const int t = threadIdx.x;
    const int i = t >> 2, nq = t & 3, n0 = nq * 16;
    const int c = h * 4096 + i * 64 + j;

    u64t dAre2[8], dAim2[8], ndAim2[8], C2re2[8], nC2im2[8], zre2[8], zim2[8];

#pragma unroll
    for (int p = 0; p < 8; p++) {
        float dare[2], daim[2], c2re[2], c2im[2];
#pragma unroll
        for (int e = 0; e < 2; e++) {
            const int n = n0 + 2 * p + e;
            const float are = Are[n], aim = Aim[n];
            const float dre = 1.f - 0.05f * are, dim = -0.05f * aim;   // 1 - DT*A/2
            const float nre = 1.f + 0.05f * are, nim = 0.05f * aim;    // 1 + DT*A/2
            const float inv = 1.f / (dre * dre + dim * dim);
            dare[e] = (nre * dre + nim * dim) * inv;                   // dA
            daim[e] = (nim * dre - nre * dim) * inv;
            const float dbre = 0.1f * dre * inv;                       // dB = DT/d
            const float dbim = -0.1f * dim * inv;
            const float cr = Cre[c * 64 + n], ci = Cim[c * 64 + n];
            c2re[e] = 2.f * (cr * dbre - ci * dbim);                   // 2*CB
            c2im[e] = 2.f * (cr * dbim + ci * dbre);
        }
        dAre2[p]  = pack2(dare[0], dare[1]);
        dAim2[p]  = pack2(daim[0], daim[1]);
        ndAim2[p] = pack2(-daim[0], -daim[1]);
        C2re2[p]  = pack2(c2re[0], c2re[1]);
        nC2im2[p] = pack2(-c2im[0], -c2im[1]);
        zre2[p] = 0ull; zim2[p] = 0ull;
    }
    const float ddv = (nq == 0) ? Dd[c] : 0.f;

    __shared__ __align__(16) float KsT[64 * 68];   // [i][r], stride 68
    __shared__ __align__(16) float QsT[64 * 68];
    __shared__ __align__(16) float Vs[64];
    __shared__ float sVals[8 * 257];               // [8 steps][256 threads]

    for (int ch = 0; ch < 16; ch++) {
        const int s0 = ch * 64;
        __syncthreads();
        for (int idx = t; idx < 4096; idx += 256) {
            const int r = idx >> 6, cc = idx & 63;   // coalesced gmem read
            KsT[cc * 68 + r] = g_K[(s0 + r) * 512 + h * 64 + cc];
            QsT[cc * 68 + r] = g_Q[(s0 + r) * 512 + h * 64 + cc];
        }
        if (t < 64) Vs[t] = g_V[(s0 + t) * 512 + h * 64 + j];
        __syncthreads();

        for (int g = 0; g < 8; g++) {              // 8 reduce-groups of 8 steps
#pragma unroll
            for (int q4 = 0; q4 < 2; q4++) {       // 2 quads of 4 steps
                const int r0 = g * 8 + q4 * 4;
                const float4 kk = *(const float4*)&KsT[i * 68 + r0];
                const float4 qq = *(const float4*)&QsT[i * 68 + r0];
                const float4 vv = *(const float4*)&Vs[r0];
                float us[4] = {kk.x * vv.x, kk.y * vv.y, kk.z * vv.z, kk.w * vv.w};
                float qs[4] = {qq.x, qq.y, qq.z, qq.w};
#pragma unroll
                for (int rr = 0; rr < 4; rr++) {
                    const float u  = us[rr];
                    const u64t u2  = pack2(u, u);
                    u64t acc = 0ull;
#pragma unroll
                    for (int p = 0; p < 8; p++) {
                        // zre' = dre*zre - dim*zim + u ; zim' = dre*zim + dim*zre
                        const u64t a = fma2(ndAim2[p], zim2[p], u2);
                        const u64t b = mul2(dAim2[p], zre2[p]);
                        zim2[p] = fma2(dAre2[p], zim2[p], b);
                        zre2[p] = fma2(dAre2[p], zre2[p], a);
                        acc = fma2(C2re2[p], zre2[p], acc);
                        acc = fma2(nC2im2[p], zim2[p], acc);
                    }
                    float alo, ahi; unpack2(acc, alo, ahi);
                    const float yp = alo + ahi;
                    sVals[(q4 * 4 + rr) * 257 + t] = (yp + ddv * u) * qs[rr];
                }
            }
            __syncthreads();
            {   // reduce 256 partials for each of 8 steps
                const int r = t >> 5, part = t & 31;
                const float* row = sVals + r * 257 + part;
                float s = 0.f;
#pragma unroll
                for (int m = 0; m < 8; m++) s += row[32 * m];
                s += __shfl_xor_sync(0xffffffffu, s, 1);
                s += __shfl_xor_sync(0xffffffffu, s, 2);
                s += __shfl_xor_sync(0xffffffffu, s, 4);
                s += __shfl_xor_sync(0xffffffffu, s, 8);
                s += __shfl_xor_sync(0xffffffffu, s, 16);
                if (part == 0)
                    g_Ot[(h * 64 + j) * 1024 + s0 + g * 8 + r] = s;
            }
            __syncthreads();
        }
    }
}

// ---------------------------------------------------------------------------
// GEMM 2: out[s,n] = sum_k g_Ot[k][s] * WO[n,k], double-buffered
// ---------------------------------------------------------------------------
__global__ __launch_bounds__(256) void gemm_out(
    const float* __restrict__ WO, float* __restrict__ out)
{
    __shared__ __align__(16) float As[2][16][64];
    __shared__ __align__(16) float Bs[2][16][64];

    const int t  = threadIdx.x;
    const int tx = t & 15, ty = t >> 4;
    const int m0 = blockIdx.y * 64, n0 = blockIdx.x * 64;
    const int lr = t >> 2, lk = (t & 3) * 4;
    const int kk = t >> 4, mm = (t & 15) * 4;

    float4 av = *(const float4*)(g_Ot + kk * 1024 + m0 + mm);
    float4 bv = *(const float4*)(WO + (n0 + lr) * 512 + lk);
    *(float4*)&As[0][kk][mm] = av;
    Bs[0][lk+0][lr] = bv.x; Bs[0][lk+1][lr] = bv.y; Bs[0][lk+2][lr] = bv.z; Bs[0][lk+3][lr] = bv.w;
    __syncthreads();

    u64t acc2[4][2] = {};
    int buf = 0;

    for (int k0 = 0; k0 < 512; k0 += 16) {
        if (k0 + 16 < 512) {
            av = *(const float4*)(g_Ot + (k0 + 16 + kk) * 1024 + m0 + mm);
            bv = *(const float4*)(WO + (n0 + lr) * 512 + k0 + 16 + lk);
        }
#pragma unroll
        for (int k = 0; k < 16; k++) {
            float4 a4 = *(const float4*)&As[buf][k][ty * 4];
            float4 b4 = *(const float4*)&Bs[buf][k][tx * 4];
            const u64t b01 = pack2(b4.x, b4.y);
            const u64t b23 = pack2(b4.z, b4.w);
            float ar[4] = {a4.x, a4.y, a4.z, a4.w};
#pragma unroll
            for (int e = 0; e < 4; e++) {
                const u64t ae = pack2(ar[e], ar[e]);
                acc2[e][0] = fma2(ae, b01, acc2[e][0]);
                acc2[e][1] = fma2(ae, b23, acc2[e][1]);
            }
        }
        if (k0 + 16 < 512) {
            const int nb = buf ^ 1;
            *(float4*)&As[nb][kk][mm] = av;
            Bs[nb][lk+0][lr] = bv.x; Bs[nb][lk+1][lr] = bv.y; Bs[nb][lk+2][lr] = bv.z; Bs[nb][lk+3][lr] = bv.w;
            __syncthreads();
            buf = nb;
        }
    }
#pragma unroll
    for (int e = 0; e < 4; e++) {
        float4 v;
        unpack2(acc2[e][0], v.x, v.y);
        unpack2(acc2[e][1], v.z, v.w);
        *(float4*)(out + (m0 + ty * 4 + e) * 512 + n0 + tx * 4) = v;
    }
}

// ---------------------------------------------------------------------------
extern "C" void kernel_launch(void* const* d_in, const int* in_sizes, int n_in,
                              void* d_out, int out_size)
{
    (void)in_sizes; (void)n_in; (void)out_size;
    const float* x   = (const float*)d_in[0];
    const float* WQ  = (const float*)d_in[1];
    const float* WK  = (const float*)d_in[2];
    const float* WV  = (const float*)d_in[3];
    const float* WO  = (const float*)d_in[4];
    const float* Cs  = (const float*)d_in[5];
    const float* Ds  = (const float*)d_in[6];
    const float* Are = (const float*)d_in[7];
    const float* Aim = (const float*)d_in[8];
    const float* Cre = (const float*)d_in[9];
    const float* Cim = (const float*)d_in[10];
    const float* Ddg = (const float*)d_in[11];

    gemm_qkv  <<<dim3(8, 16, 3), 256>>>(x, WQ, WK, WV);
    shift_conv<<<512, 256>>>(Cs, Ds);
    scan_s4d  <<<512, 256>>>(Are, Aim, Cre, Cim, Ddg);
    gemm_out  <<<dim3(8, 16), 256>>>(WO, (float*)d_out);
}

// round 15
// speedup vs baseline: 1.1000x; 1.1000x over previous
#include <cuda_runtime.h>

// ---------------------------------------------------------------------------
// H3 block: Q/K/V proj -> shift-SSM FIR on K -> per-head KV outer product ->
// S4D diagonal SSM (recurrence scan, per-chunk fused Q contraction) ->
// output projection.  B=1, S=1024, D=512, HEADS=8, DH=64, N=64, DT=0.1
// ---------------------------------------------------------------------------

#define SQ   1024
#define DD   512

__device__ float g_Q [SQ*DD];
__device__ float g_K0[SQ*DD];
__device__ float g_K [SQ*DD];
__device__ float g_V [SQ*DD];
__device__ float g_Ot[DD*SQ];   // pre-WO output, transposed [d][s]

typedef unsigned long long u64t;

__device__ __forceinline__ u64t pack2(float lo, float hi) {
    u64t r; asm("mov.b64 %0, {%1,%2};" : "=l"(r) : "f"(lo), "f"(hi)); return r;
}
__device__ __forceinline__ void unpack2(u64t v, float& lo, float& hi) {
    asm("mov.b64 {%0,%1}, %2;" : "=f"(lo), "=f"(hi) : "l"(v));
}
__device__ __forceinline__ u64t fma2(u64t a, u64t b, u64t c) {
    u64t d; asm("fma.rn.f32x2 %0, %1, %2, %3;" : "=l"(d) : "l"(a), "l"(b), "l"(c)); return d;
}
__device__ __forceinline__ u64t mul2(u64t a, u64t b) {
    u64t d; asm("mul.rn.f32x2 %0, %1, %2;" : "=l"(d) : "l"(a), "l"(b)); return d;
}

// ---------------------------------------------------------------------------
// GEMM 1: C[1024,512] = A @ W^T  (x3 via grid.z), 64x64 tile, double-buffered
// ---------------------------------------------------------------------------
__global__ __launch_bounds__(256) void gemm_qkv(
    const float* __restrict__ A,
    const float* __restrict__ WQ, const float* __restrict__ WK,
    const float* __restrict__ WV)
{
    const float* W = (blockIdx.z == 0) ? WQ : (blockIdx.z == 1) ? WK : WV;
    float*       C = (blockIdx.z == 0) ? g_Q : (blockIdx.z == 1) ? g_K0 : g_V;

    __shared__ __align__(16) float As[2][16][64];
    __shared__ __align__(16) float Bs[2][16][64];

    const int t  = threadIdx.x;
    const int tx = t & 15, ty = t >> 4;
    const int m0 = blockIdx.y * 64, n0 = blockIdx.x * 64;
    const int lr = t >> 2, lk = (t & 3) * 4;

    float4 av = *(const float4*)(A + (m0 + lr) * 512 + lk);
    float4 bv = *(const float4*)(W + (n0 + lr) * 512 + lk);
    As[0][lk+0][lr] = av.x; As[0][lk+1][lr] = av.y; As[0][lk+2][lr] = av.z; As[0][lk+3][lr] = av.w;
    Bs[0][lk+0][lr] = bv.x; Bs[0][lk+1][lr] = bv.y; Bs[0][lk+2][lr] = bv.z; Bs[0][lk+3][lr] = bv.w;
    __syncthreads();

    u64t acc2[4][2] = {};
    int buf = 0;

    for (int k0 = 0; k0 < 512; k0 += 16) {
        if (k0 + 16 < 512) {
            av = *(const float4*)(A + (m0 + lr) * 512 + k0 + 16 + lk);
            bv = *(const float4*)(W + (n0 + lr) * 512 + k0 + 16 + lk);
        }
#pragma unroll
        for (int k = 0; k < 16; k++) {
            float4 a4 = *(const float4*)&As[buf][k][ty * 4];
            float4 b4 = *(const float4*)&Bs[buf][k][tx * 4];
            const u64t b01 = pack2(b4.x, b4.y);
            const u64t b23 = pack2(b4.z, b4.w);
            float ar[4] = {a4.x, a4.y, a4.z, a4.w};
#pragma unroll
            for (int e = 0; e < 4; e++) {
                const u64t ae = pack2(ar[e], ar[e]);
                acc2[e][0] = fma2(ae, b01, acc2[e][0]);
                acc2[e][1] = fma2(ae, b23, acc2[e][1]);
            }
        }
        if (k0 + 16 < 512) {
            const int nb = buf ^ 1;
            As[nb][lk+0][lr] = av.x; As[nb][lk+1][lr] = av.y; As[nb][lk+2][lr] = av.z; As[nb][lk+3][lr] = av.w;
            Bs[nb][lk+0][lr] = bv.x; Bs[nb][lk+1][lr] = bv.y; Bs[nb][lk+2][lr] = bv.z; Bs[nb][lk+3][lr] = bv.w;
            __syncthreads();
            buf = nb;
        }
    }
#pragma unroll
    for (int e = 0; e < 4; e++) {
        float4 v;
        unpack2(acc2[e][0], v.x, v.y);
        unpack2(acc2[e][1], v.z, v.w);
        *(float4*)(C + (m0 + ty * 4 + e) * 512 + n0 + tx * 4) = v;
    }
}

// ---------------------------------------------------------------------------
// Shift-SSM FIR on K (64 taps + skip), one block per channel
// ---------------------------------------------------------------------------
__global__ __launch_bounds__(256) void shift_conv(
    const float* __restrict__ Cs, const float* __restrict__ Ds)
{
    const int d = blockIdx.x;
    __shared__ float taps[64];
    __shared__ float col[1024];
    const int t = threadIdx.x;
    if (t < 64) taps[t] = Cs[d * 64 + t];
    for (int s = t; s < 1024; s += 256) col[s] = g_K0[s * 512 + d];
    __syncthreads();
    const float dsv = Ds[d];
    for (int s = t; s < 1024; s += 256) {
        float acc = dsv * col[s];
        const int tmax = (s < 63) ? s : 63;
        for (int tt = 0; tt <= tmax; tt++) acc += taps[tt] * col[s - tt];
        g_K[s * 512 + d] = acc;
    }
}

// ---------------------------------------------------------------------------
// S4D diagonal SSM scan + per-chunk fused Q contraction.
// channel c = h*4096 + i*64 + j,  u[c,s] = K[s,h,i]*V[s,h,j]
//   z' = dA*z + u  (complex),  y = 2Re(sum_n CB*z) + Dd*u
//   O_t[h*64+j][s] = sum_i Q[s,h,i]*y[(h,i,j),s]
//
// grid = 512 (h,j); 256 threads: thread = (i = t>>2, nq = t&3 -> 16 modes).
// Inner loop: 24 packed FMAs + u + skip + 2 shuffles + predicated STS; the
// chunk's full y tile lands in SMEM (ySm[64][64]) and the Q contraction runs
// once per 64-step chunk (16 FMA + 2 SHFL per thread). 3 barriers/chunk.
// ---------------------------------------------------------------------------
__global__ __launch_bounds__(256) void scan_s4d(
    const float* __restrict__ Are, const float* __restrict__ Aim,
    const float* __restrict__ Cre, const float* __restrict__ Cim,
    const float* __restrict__ Dd)
{
    const int bx = blockIdx.x;
    const int h = bx >> 6, j = bx & 63;
    const int t = threadIdx.x;
    const int i = t >> 2, nq = t & 3, n0 = nq * 16;
    const int c = h * 4096 + i * 64 + j;

    u64t dAre2[8], dAim2[8], ndAim2[8], C2re2[8], nC2im2[8], zre2[8], zim2[8];

#pragma unroll
    for (int p = 0; p < 8; p++) {
        float dare[2], daim[2], c2re[2], c2im[2];
#pragma unroll
        for (int e = 0; e < 2; e++) {
            const int n = n0 + 2 * p + e;
            const float are = Are[n], aim = Aim[n];
            const float dre = 1.f - 0.05f * are, dim = -0.05f * aim;   // 1 - DT*A/2
            const float nre = 1.f + 0.05f * are, nim = 0.05f * aim;    // 1 + DT*A/2
            const float inv = 1.f / (dre * dre + dim * dim);
            dare[e] = (nre * dre + nim * dim) * inv;                   // dA
            daim[e] = (nim * dre - nre * dim) * inv;
            const float dbre = 0.1f * dre * inv;                       // dB = DT/d
            const float dbim = -0.1f * dim * inv;
            const float cr = Cre[c * 64 + n], ci = Cim[c * 64 + n];
            c2re[e] = 2.f * (cr * dbre - ci * dbim);                   // 2*CB
            c2im[e] = 2.f * (cr * dbim + ci * dbre);
        }
        dAre2[p]  = pack2(dare[0], dare[1]);
        dAim2[p]  = pack2(daim[0], daim[1]);
        ndAim2[p] = pack2(-daim[0], -daim[1]);
        C2re2[p]  = pack2(c2re[0], c2re[1]);
        nC2im2[p] = pack2(-c2im[0], -c2im[1]);
        zre2[p] = 0ull; zim2[p] = 0ull;
    }
    const float ddv = (nq == 0) ? Dd[c] : 0.f;   // skip folded once per channel

    __shared__ __align__(16) float KsT[64 * 68];   // [i][r], stride 68
    __shared__ __align__(16) float Vs[64];
    __shared__ __align__(16) float ySm[64 * 68];   // [i][r], chunk y tile

    for (int ch = 0; ch < 16; ch++) {
        const int s0 = ch * 64;
        __syncthreads();
        for (int idx = t; idx < 4096; idx += 256) {
            const int r = idx >> 6, cc = idx & 63;   // coalesced gmem read
            KsT[cc * 68 + r] = g_K[(s0 + r) * 512 + h * 64 + cc];
        }
        if (t < 64) Vs[t] = g_V[(s0 + t) * 512 + h * 64 + j];
        __syncthreads();

#pragma unroll 4
        for (int q4 = 0; q4 < 16; q4++) {          // 16 quads of 4 steps
            const int r0 = q4 * 4;
            const float4 kk = *(const float4*)&KsT[i * 68 + r0];
            const float4 vv = *(const float4*)&Vs[r0];
            float us[4] = {kk.x * vv.x, kk.y * vv.y, kk.z * vv.z, kk.w * vv.w};
#pragma unroll
            for (int rr = 0; rr < 4; rr++) {
                const float u  = us[rr];
                const u64t u2  = pack2(u, u);
                u64t acc = 0ull;
#pragma unroll
                for (int p = 0; p < 8; p++) {
                    // zre' = dre*zre - dim*zim + u ; zim' = dre*zim + dim*zre
                    const u64t a = fma2(ndAim2[p], zim2[p], u2);
                    const u64t b = mul2(dAim2[p], zre2[p]);
                    zim2[p] = fma2(dAre2[p], zim2[p], b);
                    zre2[p] = fma2(dAre2[p], zre2[p], a);
                    acc = fma2(C2re2[p], zre2[p], acc);
                    acc = fma2(nC2im2[p], zim2[p], acc);
                }
                float alo, ahi; unpack2(acc, alo, ahi);
                float val = alo + ahi + ddv * u;     // skip only on nq==0
                val += __shfl_xor_sync(0xffffffffu, val, 1);
                val += __shfl_xor_sync(0xffffffffu, val, 2);
                if (nq == 0) ySm[i * 68 + r0 + rr] = val;
            }
        }
        __syncthreads();
        // fused Q contraction: thread = (ss = t>>2, qi = t&3 -> 16 i's)
        {
            const int ss = t >> 2, qi = t & 3;
            const float* qg = g_Q + (s0 + ss) * 512 + h * 64 + qi * 16;
            float acc = 0.f;
#pragma unroll
            for (int m4 = 0; m4 < 4; m4++) {
                const float4 qv = *(const float4*)(qg + m4 * 4);
                const int ib = qi * 16 + m4 * 4;
                acc += qv.x * ySm[(ib + 0) * 68 + ss];
                acc += qv.y * ySm[(ib + 1) * 68 + ss];
                acc += qv.z * ySm[(ib + 2) * 68 + ss];
                acc += qv.w * ySm[(ib + 3) * 68 + ss];
            }
            acc += __shfl_xor_sync(0xffffffffu, acc, 1);
            acc += __shfl_xor_sync(0xffffffffu, acc, 2);
            if (qi == 0) g_Ot[(h * 64 + j) * 1024 + s0 + ss] = acc;
        }
    }
}

// ---------------------------------------------------------------------------
// GEMM 2: out[s,n] = sum_k g_Ot[k][s] * WO[n,k], double-buffered
// ---------------------------------------------------------------------------
__global__ __launch_bounds__(256) void gemm_out(
    const float* __restrict__ WO, float* __restrict__ out)
{
    __shared__ __align__(16) float As[2][16][64];
    __shared__ __align__(16) float Bs[2][16][64];

    const int t  = threadIdx.x;
    const int tx = t & 15, ty = t >> 4;
    const int m0 = blockIdx.y * 64, n0 = blockIdx.x * 64;
    const int lr = t >> 2, lk = (t & 3) * 4;
    const int kk = t >> 4, mm = (t & 15) * 4;

    float4 av = *(const float4*)(g_Ot + kk * 1024 + m0 + mm);
    float4 bv = *(const float4*)(WO + (n0 + lr) * 512 + lk);
    *(float4*)&As[0][kk][mm] = av;
    Bs[0][lk+0][lr] = bv.x; Bs[0][lk+1][lr] = bv.y; Bs[0][lk+2][lr] = bv.z; Bs[0][lk+3][lr] = bv.w;
    __syncthreads();

    u64t acc2[4][2] = {};
    int buf = 0;

    for (int k0 = 0; k0 < 512; k0 += 16) {
        if (k0 + 16 < 512) {
            av = *(const float4*)(g_Ot + (k0 + 16 + kk) * 1024 + m0 + mm);
            bv = *(const float4*)(WO + (n0 + lr) * 512 + k0 + 16 + lk);
        }
#pragma unroll
        for (int k = 0; k < 16; k++) {
            float4 a4 = *(const float4*)&As[buf][k][ty * 4];
            float4 b4 = *(const float4*)&Bs[buf][k][tx * 4];
            const u64t b01 = pack2(b4.x, b4.y);
            const u64t b23 = pack2(b4.z, b4.w);
            float ar[4] = {a4.x, a4.y, a4.z, a4.w};
#pragma unroll
            for (int e = 0; e < 4; e++) {
                const u64t ae = pack2(ar[e], ar[e]);
                acc2[e][0] = fma2(ae, b01, acc2[e][0]);
                acc2[e][1] = fma2(ae, b23, acc2[e][1]);
            }
        }
        if (k0 + 16 < 512) {
            const int nb = buf ^ 1;
            *(float4*)&As[nb][kk][mm] = av;
            Bs[nb][lk+0][lr] = bv.x; Bs[nb][lk+1][lr] = bv.y; Bs[nb][lk+2][lr] = bv.z; Bs[nb][lk+3][lr] = bv.w;
            __syncthreads();
            buf = nb;
        }
    }
#pragma unroll
    for (int e = 0; e < 4; e++) {
        float4 v;
        unpack2(acc2[e][0], v.x, v.y);
        unpack2(acc2[e][1], v.z, v.w);
        *(float4*)(out + (m0 + ty * 4 + e) * 512 + n0 + tx * 4) = v;
    }
}

// ---------------------------------------------------------------------------
extern "C" void kernel_launch(void* const* d_in, const int* in_sizes, int n_in,
                              void* d_out, int out_size)
{
    (void)in_sizes; (void)n_in; (void)out_size;
    const float* x   = (const float*)d_in[0];
    const float* WQ  = (const float*)d_in[1];
    const float* WK  = (const float*)d_in[2];
    const float* WV  = (const float*)d_in[3];
    const float* WO  = (const float*)d_in[4];
    const float* Cs  = (const float*)d_in[5];
    const float* Ds  = (const float*)d_in[6];
    const float* Are = (const float*)d_in[7];
    const float* Aim = (const float*)d_in[8];
    const float* Cre = (const float*)d_in[9];
    const float* Cim = (const float*)d_in[10];
    const float* Ddg = (const float*)d_in[11];

    gemm_qkv  <<<dim3(8, 16, 3), 256>>>(x, WQ, WK, WV);
    shift_conv<<<512, 256>>>(Cs, Ds);
    scan_s4d  <<<512, 256>>>(Are, Aim, Cre, Cim, Ddg);
    gemm_out  <<<dim3(8, 16), 256>>>(WO, (float*)d_out);
}

// round 16
// speedup vs baseline: 1.1157x; 1.0143x over previous
#include <cuda_runtime.h>

// ---------------------------------------------------------------------------
// H3 block: Q/K/V proj -> shift-SSM FIR on K -> per-head KV outer product ->
// S4D diagonal SSM (recurrence scan, per-chunk fused Q contraction) ->
// output projection.  B=1, S=1024, D=512, HEADS=8, DH=64, N=64, DT=0.1
// ---------------------------------------------------------------------------

#define SQ   1024
#define DD   512

__device__ float g_Q [SQ*DD];
__device__ float g_K0[SQ*DD];
__device__ float g_K [SQ*DD];
__device__ float g_V [SQ*DD];
__device__ float g_Ot[DD*SQ];   // pre-WO output, transposed [d][s]

typedef unsigned long long u64t;

__device__ __forceinline__ u64t pack2(float lo, float hi) {
    u64t r; asm("mov.b64 %0, {%1,%2};" : "=l"(r) : "f"(lo), "f"(hi)); return r;
}
__device__ __forceinline__ void unpack2(u64t v, float& lo, float& hi) {
    asm("mov.b64 {%0,%1}, %2;" : "=f"(lo), "=f"(hi) : "l"(v));
}
__device__ __forceinline__ u64t fma2(u64t a, u64t b, u64t c) {
    u64t d; asm("fma.rn.f32x2 %0, %1, %2, %3;" : "=l"(d) : "l"(a), "l"(b), "l"(c)); return d;
}
__device__ __forceinline__ u64t mul2(u64t a, u64t b) {
    u64t d; asm("mul.rn.f32x2 %0, %1, %2;" : "=l"(d) : "l"(a), "l"(b)); return d;
}

// ---------------------------------------------------------------------------
// GEMM 1: C[1024,512] = A @ W^T  (x3 via grid.z), 64x64 tile, double-buffered
// ---------------------------------------------------------------------------
__global__ __launch_bounds__(256) void gemm_qkv(
    const float* __restrict__ A,
    const float* __restrict__ WQ, const float* __restrict__ WK,
    const float* __restrict__ WV)
{
    const float* W = (blockIdx.z == 0) ? WQ : (blockIdx.z == 1) ? WK : WV;
    float*       C = (blockIdx.z == 0) ? g_Q : (blockIdx.z == 1) ? g_K0 : g_V;

    __shared__ __align__(16) float As[2][16][64];
    __shared__ __align__(16) float Bs[2][16][64];

    const int t  = threadIdx.x;
    const int tx = t & 15, ty = t >> 4;
    const int m0 = blockIdx.y * 64, n0 = blockIdx.x * 64;
    const int lr = t >> 2, lk = (t & 3) * 4;

    float4 av = *(const float4*)(A + (m0 + lr) * 512 + lk);
    float4 bv = *(const float4*)(W + (n0 + lr) * 512 + lk);
    As[0][lk+0][lr] = av.x; As[0][lk+1][lr] = av.y; As[0][lk+2][lr] = av.z; As[0][lk+3][lr] = av.w;
    Bs[0][lk+0][lr] = bv.x; Bs[0][lk+1][lr] = bv.y; Bs[0][lk+2][lr] = bv.z; Bs[0][lk+3][lr] = bv.w;
    __syncthreads();

    u64t acc2[4][2] = {};
    int buf = 0;

    for (int k0 = 0; k0 < 512; k0 += 16) {
        if (k0 + 16 < 512) {
            av = *(const float4*)(A + (m0 + lr) * 512 + k0 + 16 + lk);
            bv = *(const float4*)(W + (n0 + lr) * 512 + k0 + 16 + lk);
        }
#pragma unroll
        for (int k = 0; k < 16; k++) {
            float4 a4 = *(const float4*)&As[buf][k][ty * 4];
            float4 b4 = *(const float4*)&Bs[buf][k][tx * 4];
            const u64t b01 = pack2(b4.x, b4.y);
            const u64t b23 = pack2(b4.z, b4.w);
            float ar[4] = {a4.x, a4.y, a4.z, a4.w};
#pragma unroll
            for (int e = 0; e < 4; e++) {
                const u64t ae = pack2(ar[e], ar[e]);
                acc2[e][0] = fma2(ae, b01, acc2[e][0]);
                acc2[e][1] = fma2(ae, b23, acc2[e][1]);
            }
        }
        if (k0 + 16 < 512) {
            const int nb = buf ^ 1;
            As[nb][lk+0][lr] = av.x; As[nb][lk+1][lr] = av.y; As[nb][lk+2][lr] = av.z; As[nb][lk+3][lr] = av.w;
            Bs[nb][lk+0][lr] = bv.x; Bs[nb][lk+1][lr] = bv.y; Bs[nb][lk+2][lr] = bv.z; Bs[nb][lk+3][lr] = bv.w;
            __syncthreads();
            buf = nb;
        }
    }
#pragma unroll
    for (int e = 0; e < 4; e++) {
        float4 v;
        unpack2(acc2[e][0], v.x, v.y);
        unpack2(acc2[e][1], v.z, v.w);
        *(float4*)(C + (m0 + ty * 4 + e) * 512 + n0 + tx * 4) = v;
    }
}

// ---------------------------------------------------------------------------
// Shift-SSM FIR on K (64 taps + skip), one block per channel
// ---------------------------------------------------------------------------
__global__ __launch_bounds__(256) void shift_conv(
    const float* __restrict__ Cs, const float* __restrict__ Ds)
{
    const int d = blockIdx.x;
    __shared__ float taps[64];
    __shared__ float col[1024];
    const int t = threadIdx.x;
    if (t < 64) taps[t] = Cs[d * 64 + t];
    for (int s = t; s < 1024; s += 256) col[s] = g_K0[s * 512 + d];
    __syncthreads();
    const float dsv = Ds[d];
    for (int s = t; s < 1024; s += 256) {
        float acc = dsv * col[s];
        const int tmax = (s < 63) ? s : 63;
        for (int tt = 0; tt <= tmax; tt++) acc += taps[tt] * col[s - tt];
        g_K[s * 512 + d] = acc;
    }
}

// ---------------------------------------------------------------------------
// S4D diagonal SSM scan + per-chunk fused Q contraction, shuffle-free.
// channel c = h*4096 + i*64 + j,  u[c,s] = K[s,h,i]*V[s,h,j]
//   z' = dA*z + u  (complex),  y = 2Re(sum_n CB*z) + Dd*u
//   O_t[h*64+j][s] = sum_i Q[s,h,i]*y[(h,i,j),s]
//
// grid = 512 (h,j); 256 threads: thread = (i = t>>2, nq = t&3 -> 16 modes).
// Inner loop: 24 packed FMAs + u + 2 scalar ops + 1 conflict-free STS.
// Each nq stores its quarter-partial into its own ySm plane; the per-chunk
// contraction sums the 4 planes. K/V tiles are ping-ponged so the next
// chunk's fill overlaps the contraction: 2 barriers per 64-step chunk.
// Dynamic SMEM: 2*64*68 (K) + 2*64 (V) + 4*4353 (y planes) floats = ~105 KB.
// ---------------------------------------------------------------------------
#define YPLANE 4353                 // 64*68 + 1 -> nq offset of 1 bank
#define SMEM_SCAN ((2*64*68 + 2*64 + 4*YPLANE) * 4)

__global__ __launch_bounds__(256) void scan_s4d(
    const float* __restrict__ Are, const float* __restrict__ Aim,
    const float* __restrict__ Cre, const float* __restrict__ Cim,
    const float* __restrict__ Dd)
{
    extern __shared__ __align__(16) float sm[];
    float* sK = sm;                      // [2][64*68]
    float* sV = sm + 2 * 64 * 68;        // [2][64]
    float* sY = sV + 2 * 64;             // [4][YPLANE]

    const int bx = blockIdx.x;
    const int h = bx >> 6, j = bx & 63;
    const int t = threadIdx.x;
    const int i = t >> 2, nq = t & 3, n0 = nq * 16;
    const int c = h * 4096 + i * 64 + j;

    u64t dAre2[8], dAim2[8], ndAim2[8], C2re2[8], nC2im2[8], zre2[8], zim2[8];

#pragma unroll
    for (int p = 0; p < 8; p++) {
        float dare[2], daim[2], c2re[2], c2im[2];
#pragma unroll
        for (int e = 0; e < 2; e++) {
            const int n = n0 + 2 * p + e;
            const float are = Are[n], aim = Aim[n];
            const float dre = 1.f - 0.05f * are, dim = -0.05f * aim;   // 1 - DT*A/2
            const float nre = 1.f + 0.05f * are, nim = 0.05f * aim;    // 1 + DT*A/2
            const float inv = 1.f / (dre * dre + dim * dim);
            dare[e] = (nre * dre + nim * dim) * inv;                   // dA
            daim[e] = (nim * dre - nre * dim) * inv;
            const float dbre = 0.1f * dre * inv;                       // dB = DT/d
            const float dbim = -0.1f * dim * inv;
            const float cr = Cre[c * 64 + n], ci = Cim[c * 64 + n];
            c2re[e] = 2.f * (cr * dbre - ci * dbim);                   // 2*CB
            c2im[e] = 2.f * (cr * dbim + ci * dbre);
        }
        dAre2[p]  = pack2(dare[0], dare[1]);
        dAim2[p]  = pack2(daim[0], daim[1]);
        ndAim2[p] = pack2(-daim[0], -daim[1]);
        C2re2[p]  = pack2(c2re[0], c2re[1]);
        nC2im2[p] = pack2(-c2im[0], -c2im[1]);
        zre2[p] = 0ull; zim2[p] = 0ull;
    }
    const float ddv = (nq == 0) ? Dd[c] : 0.f;   // skip folded on plane 0 only
    float* yOut = sY + nq * YPLANE + i * 68;

    // fill chunk 0 into buffer 0
    for (int idx = t; idx < 4096; idx += 256) {
        const int r = idx >> 6, cc = idx & 63;
        sK[cc * 68 + r] = g_K[r * 512 + h * 64 + cc];
    }
    if (t < 64) sV[t] = g_V[t * 512 + h * 64 + j];
    __syncthreads();

    for (int ch = 0; ch < 16; ch++) {
        const int s0 = ch * 64;
        const int buf = ch & 1;
        const float* kT = sK + buf * (64 * 68);
        const float* vT = sV + buf * 64;

#pragma unroll 4
        for (int q4 = 0; q4 < 16; q4++) {          // 16 quads of 4 steps
            const int r0 = q4 * 4;
            const float4 kk = *(const float4*)&kT[i * 68 + r0];
            const float4 vv = *(const float4*)&vT[r0];
            float us[4] = {kk.x * vv.x, kk.y * vv.y, kk.z * vv.z, kk.w * vv.w};
#pragma unroll
            for (int rr = 0; rr < 4; rr++) {
                const float u  = us[rr];
                const u64t u2  = pack2(u, u);
                u64t acc = 0ull;
#pragma unroll
                for (int p = 0; p < 8; p++) {
                    // zre' = dre*zre - dim*zim + u ; zim' = dre*zim + dim*zre
                    const u64t a = fma2(ndAim2[p], zim2[p], u2);
                    const u64t b = mul2(dAim2[p], zre2[p]);
                    zim2[p] = fma2(dAre2[p], zim2[p], b);
                    zre2[p] = fma2(dAre2[p], zre2[p], a);
                    acc = fma2(C2re2[p], zre2[p], acc);
                    acc = fma2(nC2im2[p], zim2[p], acc);
                }
                float alo, ahi; unpack2(acc, alo, ahi);
                yOut[r0 + rr] = fmaf(ddv, u, alo + ahi);   // conflict-free STS
            }
        }
        __syncthreads();

        // prefetch next chunk K/V into the other buffer (overlaps contraction)
        if (ch < 15) {
            const int s1 = s0 + 64;
            float* kN = sK + (buf ^ 1) * (64 * 68);
            for (int idx = t; idx < 4096; idx += 256) {
                const int r = idx >> 6, cc = idx & 63;
                kN[cc * 68 + r] = g_K[(s1 + r) * 512 + h * 64 + cc];
            }
            if (t < 64) sV[(buf ^ 1) * 64 + t] = g_V[(s1 + t) * 512 + h * 64 + j];
        }

        // fused Q contraction: thread = (ss = t>>2, qi = t&3 -> 16 i's)
        {
            const int ss = t >> 2, qi = t & 3;
            const float* qg = g_Q + (s0 + ss) * 512 + h * 64 + qi * 16;
            float acc = 0.f;
#pragma unroll
            for (int m4 = 0; m4 < 4; m4++) {
                const float4 qv = *(const float4*)(qg + m4 * 4);
                const int ib = qi * 16 + m4 * 4;
                float qa[4] = {qv.x, qv.y, qv.z, qv.w};
#pragma unroll
                for (int e = 0; e < 4; e++) {
                    const int yb = (ib + e) * 68 + ss;
                    const float ysum = (sY[yb] + sY[YPLANE + yb])
                                     + (sY[2 * YPLANE + yb] + sY[3 * YPLANE + yb]);
                    acc += qa[e] * ysum;
                }
            }
            acc += __shfl_xor_sync(0xffffffffu, acc, 1);
            acc += __shfl_xor_sync(0xffffffffu, acc, 2);
            if (qi == 0) g_Ot[(h * 64 + j) * 1024 + s0 + ss] = acc;
        }
        __syncthreads();
    }
}

// ---------------------------------------------------------------------------
// GEMM 2: out[s,n] = sum_k g_Ot[k][s] * WO[n,k], double-buffered
// ---------------------------------------------------------------------------
__global__ __launch_bounds__(256) void gemm_out(
    const float* __restrict__ WO, float* __restrict__ out)
{
    __shared__ __align__(16) float As[2][16][64];
    __shared__ __align__(16) float Bs[2][16][64];

    const int t  = threadIdx.x;
    const int tx = t & 15, ty = t >> 4;
    const int m0 = blockIdx.y * 64, n0 = blockIdx.x * 64;
    const int lr = t >> 2, lk = (t & 3) * 4;
    const int kk = t >> 4, mm = (t & 15) * 4;

    float4 av = *(const float4*)(g_Ot + kk * 1024 + m0 + mm);
    float4 bv = *(const float4*)(WO + (n0 + lr) * 512 + lk);
    *(float4*)&As[0][kk][mm] = av;
    Bs[0][lk+0][lr] = bv.x; Bs[0][lk+1][lr] = bv.y; Bs[0][lk+2][lr] = bv.z; Bs[0][lk+3][lr] = bv.w;
    __syncthreads();

    u64t acc2[4][2] = {};
    int buf = 0;

    for (int k0 = 0; k0 < 512; k0 += 16) {
        if (k0 + 16 < 512) {
            av = *(const float4*)(g_Ot + (k0 + 16 + kk) * 1024 + m0 + mm);
            bv = *(const float4*)(WO + (n0 + lr) * 512 + k0 + 16 + lk);
        }
#pragma unroll
        for (int k = 0; k < 16; k++) {
            float4 a4 = *(const float4*)&As[buf][k][ty * 4];
            float4 b4 = *(const float4*)&Bs[buf][k][tx * 4];
            const u64t b01 = pack2(b4.x, b4.y);
            const u64t b23 = pack2(b4.z, b4.w);
            float ar[4] = {a4.x, a4.y, a4.z, a4.w};
#pragma unroll
            for (int e = 0; e < 4; e++) {
                const u64t ae = pack2(ar[e], ar[e]);
                acc2[e][0] = fma2(ae, b01, acc2[e][0]);
                acc2[e][1] = fma2(ae, b23, acc2[e][1]);
            }
        }
        if (k0 + 16 < 512) {
            const int nb = buf ^ 1;
            *(float4*)&As[nb][kk][mm] = av;
            Bs[nb][lk+0][lr] = bv.x; Bs[nb][lk+1][lr] = bv.y; Bs[nb][lk+2][lr] = bv.z; Bs[nb][lk+3][lr] = bv.w;
            __syncthreads();
            buf = nb;
        }
    }
#pragma unroll
    for (int e = 0; e < 4; e++) {
        float4 v;
        unpack2(acc2[e][0], v.x, v.y);
        unpack2(acc2[e][1], v.z, v.w);
        *(float4*)(out + (m0 + ty * 4 + e) * 512 + n0 + tx * 4) = v;
    }
}

// ---------------------------------------------------------------------------
extern "C" void kernel_launch(void* const* d_in, const int* in_sizes, int n_in,
                              void* d_out, int out_size)
{
    (void)in_sizes; (void)n_in; (void)out_size;
    const float* x   = (const float*)d_in[0];
    const float* WQ  = (const float*)d_in[1];
    const float* WK  = (const float*)d_in[2];
    const float* WV  = (const float*)d_in[3];
    const float* WO  = (const float*)d_in[4];
    const float* Cs  = (const float*)d_in[5];
    const float* Ds  = (const float*)d_in[6];
    const float* Are = (const float*)d_in[7];
    const float* Aim = (const float*)d_in[8];
    const float* Cre = (const float*)d_in[9];
    const float* Cim = (const float*)d_in[10];
    const float* Ddg = (const float*)d_in[11];

    cudaFuncSetAttribute(scan_s4d,
                         cudaFuncAttributeMaxDynamicSharedMemorySize,
                         SMEM_SCAN);

    gemm_qkv  <<<dim3(8, 16, 3), 256>>>(x, WQ, WK, WV);
    shift_conv<<<512, 256>>>(Cs, Ds);
    scan_s4d  <<<512, 256, SMEM_SCAN>>>(Are, Aim, Cre, Cim, Ddg);
    gemm_out  <<<dim3(8, 16), 256>>>(WO, (float*)d_out);
}